// round 8
// baseline (speedup 1.0000x reference)
#include <cuda_runtime.h>
#include <math.h>

// Problem constants (fixed by the reference)
#define F_IN 503
#define CC   32
#define MAXN 100000
#define MAXE 3200000
#define RPB  256      // rows per GEMM block (= threads per block)
#define KT   32       // k-tile
#define NEG  0.2f

// ---------------- scratch (static __device__ arrays; allocation-free) -------
__device__ float g_xl[(size_t)MAXN * CC];     // transformed node features [N,32]
__device__ float g_asrc[MAXN];
__device__ float g_adst[MAXN];
__device__ int   g_deg[MAXN];                 // in-degree incl. self loop
__device__ int   g_scan[MAXN];
__device__ int   g_rowptr[MAXN + 1];
__device__ int   g_cursor[MAXN];
__device__ int   g_bsum[256];
__device__ int   g_boff[256];
__device__ unsigned long long g_csr[MAXE + MAXN];   // packed (src:int, w:float)
__device__ float g_hw[MAXN];                  // h[v] . Ww
__device__ float g_scalars[4];   // [0]=sum(ew), [1]=k_edge, [2]=mean(ew)

// ---------------- init: deg=1 (self loops), scalars ------------------------
__global__ void k_init(const float* __restrict__ W_edge,
                       const float* __restrict__ att_edge, int nN) {
    int i = blockIdx.x * blockDim.x + threadIdx.x;
    if (i < nN) g_deg[i] = 1;
    if (i == 0) {
        g_scalars[0] = 0.f;
        float ke = 0.f;
        #pragma unroll
        for (int c = 0; c < CC; c++) ke += W_edge[c] * att_edge[c];
        g_scalars[1] = ke;   // a_edge = k_edge * edge_weight
    }
}

// ---------------- degree count + edge_weight sum ----------------------------
__global__ void k_deg_mean(const int* __restrict__ ei,
                           const float* __restrict__ ew, int nE) {
    int tid = threadIdx.x;
    float sum = 0.f;
    for (int i = blockIdx.x * blockDim.x + tid; i < nE;
         i += gridDim.x * blockDim.x) {
        atomicAdd(&g_deg[ei[nE + i]], 1);
        sum += ew[i];
    }
    __shared__ float red[256];
    red[tid] = sum;
    __syncthreads();
    for (int s = 128; s > 0; s >>= 1) {
        if (tid < s) red[tid] += red[tid + s];
        __syncthreads();
    }
    if (tid == 0) atomicAdd(&g_scalars[0], red[0]);
}

// ---------------- GEMM: xl = x @ W^T, fused a_src/a_dst ---------------------
__global__ void __launch_bounds__(RPB, 2)
k_gemm(const float* __restrict__ x, const float* __restrict__ W,
       const float* __restrict__ att_src, const float* __restrict__ att_dst,
       int nN) {
    extern __shared__ unsigned char sm[];
    unsigned long long* Wp = (unsigned long long*)sm;            // F_IN*16 pairs
    float* xs = (float*)(sm + (size_t)F_IN * 16 * 8);            // RPB*(KT+1)

    int tid = threadIdx.x;
    for (int i = tid; i < F_IN * 16; i += RPB) {
        int k = i >> 4, c2 = i & 15;
        float lo = W[(2 * c2) * F_IN + k];
        float hi = W[(2 * c2 + 1) * F_IN + k];
        unsigned long long p;
        asm("mov.b64 %0, {%1, %2};" : "=l"(p) : "f"(lo), "f"(hi));
        Wp[i] = p;
    }

    int row = blockIdx.x * RPB + tid;
    unsigned long long acc[16];
    #pragma unroll
    for (int j = 0; j < 16; j++) acc[j] = 0ull;

    for (int kt = 0; kt < F_IN; kt += KT) {
        int kw = min(KT, F_IN - kt);
        __syncthreads();
        for (int i = tid; i < RPB * kw; i += RPB) {
            int r = i / kw, k = i - r * kw;
            int gr = blockIdx.x * RPB + r;
            xs[r * (KT + 1) + k] = (gr < nN) ? x[(size_t)gr * F_IN + kt + k] : 0.f;
        }
        __syncthreads();
        const float* xrow = &xs[tid * (KT + 1)];
        if (kw == KT) {
            #pragma unroll
            for (int k = 0; k < KT; k++) {
                float xv = xrow[k];
                unsigned long long xx;
                asm("mov.b64 %0, {%1, %1};" : "=l"(xx) : "f"(xv));
                const ulonglong2* wr = (const ulonglong2*)&Wp[(kt + k) * 16];
                #pragma unroll
                for (int j = 0; j < 8; j++) {
                    ulonglong2 wp = wr[j];
                    asm("fma.rn.f32x2 %0, %1, %2, %0;" : "+l"(acc[2 * j])     : "l"(xx), "l"(wp.x));
                    asm("fma.rn.f32x2 %0, %1, %2, %0;" : "+l"(acc[2 * j + 1]) : "l"(xx), "l"(wp.y));
                }
            }
        } else {
            for (int k = 0; k < kw; k++) {
                float xv = xrow[k];
                unsigned long long xx;
                asm("mov.b64 %0, {%1, %1};" : "=l"(xx) : "f"(xv));
                const ulonglong2* wr = (const ulonglong2*)&Wp[(kt + k) * 16];
                #pragma unroll
                for (int j = 0; j < 8; j++) {
                    ulonglong2 wp = wr[j];
                    asm("fma.rn.f32x2 %0, %1, %2, %0;" : "+l"(acc[2 * j])     : "l"(xx), "l"(wp.x));
                    asm("fma.rn.f32x2 %0, %1, %2, %0;" : "+l"(acc[2 * j + 1]) : "l"(xx), "l"(wp.y));
                }
            }
        }
    }

    if (row < nN) {
        float as = 0.f, ad = 0.f;
        unsigned long long* dst = (unsigned long long*)(g_xl + (size_t)row * CC);
        #pragma unroll
        for (int j = 0; j < 16; j++) {
            dst[j] = acc[j];
            float lo, hi;
            asm("mov.b64 {%0, %1}, %2;" : "=f"(lo), "=f"(hi) : "l"(acc[j]));
            as += lo * att_src[2 * j] + hi * att_src[2 * j + 1];
            ad += lo * att_dst[2 * j] + hi * att_dst[2 * j + 1];
        }
        g_asrc[row] = as;
        g_adst[row] = ad;
    }
}

// ---------------- scan (exclusive prefix of deg -> rowptr) ------------------
__global__ void k_scan1(int nN) {
    __shared__ int sh[1024];
    int tid = threadIdx.x;
    int i = blockIdx.x * 1024 + tid;
    int v = (i < nN) ? g_deg[i] : 0;
    sh[tid] = v;
    __syncthreads();
    for (int off = 1; off < 1024; off <<= 1) {
        int t = (tid >= off) ? sh[tid - off] : 0;
        __syncthreads();
        sh[tid] += t;
        __syncthreads();
    }
    if (i < nN) g_scan[i] = sh[tid];
    if (tid == 1023) g_bsum[blockIdx.x] = sh[1023];
}

__global__ void k_scan2(int nb, int nE) {
    int run = 0;
    for (int b = 0; b < nb; b++) {
        int t = g_bsum[b];
        g_boff[b] = run;
        run += t;
    }
    g_scalars[2] = g_scalars[0] / (float)nE;   // mean edge weight
}

__global__ void k_scan3(int nN, int nE) {
    int i = blockIdx.x * blockDim.x + threadIdx.x;
    if (i < nN) {
        int ex = g_scan[i] - g_deg[i] + g_boff[i >> 10];
        g_rowptr[i] = ex;
        g_cursor[i] = ex;
    }
    if (i == 0) g_rowptr[nN] = nN + nE;
}

// ---------------- fill CSR with packed (src, edge_weight) -------------------
// Pure streaming reads + one packed 8B scattered store per edge.
__global__ void k_fill(const int* __restrict__ ei, const float* __restrict__ ew,
                       int nN, int nE) {
    int i = blockIdx.x * blockDim.x + threadIdx.x;
    if (i >= nE + nN) return;
    int s, d;
    float w;
    if (i < nE) { s = ei[i]; d = ei[nE + i]; w = ew[i]; }
    else        { s = d = i - nE;            w = g_scalars[2]; }
    int pos = atomicAdd(&g_cursor[d], 1);
    unsigned long long e = (unsigned long long)(unsigned)s |
                           ((unsigned long long)__float_as_uint(w) << 32);
    g_csr[pos] = e;
}

// ---------------- gather: softmax-aggregate + fused heads -------------------
// One warp per dst node, lane = channel. Unroll-4 software pipeline: 4
// independent entry->gather chains in flight (MLP>=4). Attention logit
// computed here: a_dst is per-warp, a_src[s] is a warp broadcast.
__global__ void __launch_bounds__(256)
k_gather(const float* __restrict__ bias_conv,
         const float* __restrict__ Wb, const float* __restrict__ bb,
         const float* __restrict__ Ww, const float* __restrict__ mask,
         float* __restrict__ out, int nN, int nE) {
    int warp = (blockIdx.x * blockDim.x + threadIdx.x) >> 5;
    int lane = threadIdx.x & 31;
    if (warp >= nN) return;
    int beg = g_rowptr[warp];
    int end = g_rowptr[warp + 1];
    float ad = g_adst[warp];
    float ke = g_scalars[1];
    float acc = 0.f, den = 0.f;

    int i = beg;
    for (; i + 4 <= end; i += 4) {
        unsigned long long e0 = g_csr[i];
        unsigned long long e1 = g_csr[i + 1];
        unsigned long long e2 = g_csr[i + 2];
        unsigned long long e3 = g_csr[i + 3];
        int s0 = (int)(unsigned)e0, s1 = (int)(unsigned)e1;
        int s2 = (int)(unsigned)e2, s3 = (int)(unsigned)e3;
        float v0 = g_xl[(size_t)s0 * CC + lane];
        float v1 = g_xl[(size_t)s1 * CC + lane];
        float v2 = g_xl[(size_t)s2 * CC + lane];
        float v3 = g_xl[(size_t)s3 * CC + lane];
        float as0 = g_asrc[s0], as1 = g_asrc[s1];
        float as2 = g_asrc[s2], as3 = g_asrc[s3];
        float a0 = fmaf(ke, __uint_as_float((unsigned)(e0 >> 32)), as0 + ad);
        float a1 = fmaf(ke, __uint_as_float((unsigned)(e1 >> 32)), as1 + ad);
        float a2 = fmaf(ke, __uint_as_float((unsigned)(e2 >> 32)), as2 + ad);
        float a3 = fmaf(ke, __uint_as_float((unsigned)(e3 >> 32)), as3 + ad);
        a0 = (a0 > 0.f) ? a0 : NEG * a0;
        a1 = (a1 > 0.f) ? a1 : NEG * a1;
        a2 = (a2 > 0.f) ? a2 : NEG * a2;
        a3 = (a3 > 0.f) ? a3 : NEG * a3;
        float x0 = __expf(a0), x1 = __expf(a1);
        float x2 = __expf(a2), x3 = __expf(a3);
        den += x0 + x1 + x2 + x3;
        acc = fmaf(x0, v0, acc);
        acc = fmaf(x1, v1, acc);
        acc = fmaf(x2, v2, acc);
        acc = fmaf(x3, v3, acc);
    }
    for (; i < end; i++) {
        unsigned long long e = g_csr[i];
        int s = (int)(unsigned)e;
        float v = g_xl[(size_t)s * CC + lane];
        float a = fmaf(ke, __uint_as_float((unsigned)(e >> 32)), g_asrc[s] + ad);
        a = (a > 0.f) ? a : NEG * a;
        float ex = __expf(a);
        den += ex;
        acc = fmaf(ex, v, acc);
    }

    float h = acc / den + bias_conv[lane];
    h = fmaxf(h, 0.f);
    float bsum = h * Wb[lane];
    float wsum = h * Ww[lane];
    #pragma unroll
    for (int o = 16; o > 0; o >>= 1) {
        bsum += __shfl_xor_sync(0xFFFFFFFFu, bsum, o);
        wsum += __shfl_xor_sync(0xFFFFFFFFu, wsum, o);
    }
    if (lane == 0) {
        g_hw[warp] = wsum;
        out[nE + warp] = (bsum + bb[0]) * mask[warp];
    }
}

// ---------------- edge output: 0.5*(hw[s]+hw[d]) + bw ----------------------
__global__ void k_edge(const int* __restrict__ ei, const float* __restrict__ bw,
                       float* __restrict__ out, int nE) {
    int i = blockIdx.x * blockDim.x + threadIdx.x;
    if (i < nE) {
        int s = ei[i], d = ei[nE + i];
        out[i] = 0.5f * (g_hw[s] + g_hw[d]) + bw[0];
    }
}

// ---------------- launch ----------------------------------------------------
extern "C" void kernel_launch(void* const* d_in, const int* in_sizes, int n_in,
                              void* d_out, int out_size) {
    const float* x         = (const float*)d_in[0];
    const int*   ei        = (const int*)d_in[1];
    const float* ew        = (const float*)d_in[2];
    const float* mask      = (const float*)d_in[3];
    const float* W_src     = (const float*)d_in[4];
    const float* att_src   = (const float*)d_in[5];
    const float* att_dst   = (const float*)d_in[6];
    const float* att_edge  = (const float*)d_in[7];
    const float* W_edge    = (const float*)d_in[8];
    const float* bias_conv = (const float*)d_in[9];
    const float* Wb        = (const float*)d_in[10];
    const float* bb        = (const float*)d_in[11];
    const float* Ww        = (const float*)d_in[12];
    const float* bw        = (const float*)d_in[13];
    float* out = (float*)d_out;

    int nN = in_sizes[3];            // input_mask: [N,1]
    int nE = in_sizes[2];            // edge_weight: [E,1]

    const int smem = F_IN * 16 * 8 + RPB * (KT + 1) * 4;   // 98176 B
    cudaFuncSetAttribute((const void*)k_gemm,
                         cudaFuncAttributeMaxDynamicSharedMemorySize, smem);

    k_init<<<(nN + 255) / 256, 256>>>(W_edge, att_edge, nN);
    k_deg_mean<<<2048, 256>>>(ei, ew, nE);
    k_gemm<<<(nN + RPB - 1) / RPB, RPB, smem>>>(x, W_src, att_src, att_dst, nN);
    int nb = (nN + 1023) / 1024;
    k_scan1<<<nb, 1024>>>(nN);
    k_scan2<<<1, 1>>>(nb, nE);
    k_scan3<<<(nN + 255) / 256, 256>>>(nN, nE);
    k_fill<<<(nE + nN + 255) / 256, 256>>>(ei, ew, nN, nE);
    k_gather<<<(nN + 7) / 8, 256>>>(bias_conv, Wb, bb, Ww, mask, out, nN, nE);
    k_edge<<<(nE + 255) / 256, 256>>>(ei, bw, out, nE);
}

// round 9
// speedup vs baseline: 1.3573x; 1.3573x over previous
#include <cuda_runtime.h>
#include <math.h>

// Problem constants (fixed by the reference)
#define F_IN 503
#define CC   32
#define MAXN 100000
#define MAXE 3200000
#define RPB  256      // rows per GEMM block (= threads per block)
#define KT   32       // k-tile
#define NEG  0.2f

// ---------------- scratch (static __device__ arrays; allocation-free) -------
__device__ float g_xl[(size_t)MAXN * CC];     // transformed node features [N,32]
__device__ float g_asrc[MAXN];
__device__ float g_adst[MAXN];
__device__ int   g_deg[MAXN];                 // in-degree (real edges only)
__device__ int   g_scan[MAXN];
__device__ int   g_rowptr[MAXN + 1];
__device__ int   g_cursor[MAXN];
__device__ int   g_bsum[256];
__device__ int   g_boff[256];
__device__ unsigned long long g_csr[MAXE + MAXN];   // packed (src:int, w:float)
__device__ float g_hw[MAXN];                  // h[v] . Ww
__device__ float g_scalars[4];   // [0]=sum(ew), [1]=k_edge, [2]=mean(ew)

// ---------------- init: deg=0, scalars --------------------------------------
__global__ void k_init(const float* __restrict__ W_edge,
                       const float* __restrict__ att_edge, int nN) {
    int i = blockIdx.x * blockDim.x + threadIdx.x;
    if (i < nN) g_deg[i] = 0;
    if (i == 0) {
        g_scalars[0] = 0.f;
        float ke = 0.f;
        #pragma unroll
        for (int c = 0; c < CC; c++) ke += W_edge[c] * att_edge[c];
        g_scalars[1] = ke;   // a_edge = k_edge * edge_weight
    }
}

// ---------------- degree count + edge_weight sum (vectorized) ---------------
__global__ void k_deg_mean(const int* __restrict__ ei,
                           const float* __restrict__ ew, int nE) {
    int tid = threadIdx.x;
    float sum = 0.f;
    int nq = nE >> 2;   // nE assumed divisible by 4 in vector part
    for (int q = blockIdx.x * blockDim.x + tid; q < nq;
         q += gridDim.x * blockDim.x) {
        int4 d4 = ((const int4*)(ei + nE))[q];
        float4 w4 = ((const float4*)ew)[q];
        atomicAdd(&g_deg[d4.x], 1);
        atomicAdd(&g_deg[d4.y], 1);
        atomicAdd(&g_deg[d4.z], 1);
        atomicAdd(&g_deg[d4.w], 1);
        sum += w4.x + w4.y + w4.z + w4.w;
    }
    // tail
    int base = nq << 2;
    for (int i = base + blockIdx.x * blockDim.x + tid; i < nE;
         i += gridDim.x * blockDim.x) {
        atomicAdd(&g_deg[ei[nE + i]], 1);
        sum += ew[i];
    }
    __shared__ float red[256];
    red[tid] = sum;
    __syncthreads();
    for (int s = 128; s > 0; s >>= 1) {
        if (tid < s) red[tid] += red[tid + s];
        __syncthreads();
    }
    if (tid == 0) atomicAdd(&g_scalars[0], red[0]);
}

// ---------------- GEMM: xl = x @ W^T, fused a_src/a_dst ---------------------
// One thread = one row. Packed f32x2 FMA: 16 acc pairs = 32 output cols.
// Fixed 32-wide k-tiles (shift/mask indexing, no runtime division); the
// final partial tile is zero-padded so the FMA loop is branch-free.
__global__ void __launch_bounds__(RPB, 2)
k_gemm(const float* __restrict__ x, const float* __restrict__ W,
       const float* __restrict__ att_src, const float* __restrict__ att_dst,
       int nN) {
    extern __shared__ unsigned char sm[];
    unsigned long long* Wp = (unsigned long long*)sm;            // 512*16 pairs
    float* xs = (float*)(sm + (size_t)512 * 16 * 8);             // RPB*(KT+1)

    int tid = threadIdx.x;
    // pack W (zero-padded to 512 k's): Wp[k*16+c2] = (W[2c2,k], W[2c2+1,k])
    for (int i = tid; i < 512 * 16; i += RPB) {
        int k = i >> 4, c2 = i & 15;
        float lo = 0.f, hi = 0.f;
        if (k < F_IN) {
            lo = W[(2 * c2) * F_IN + k];
            hi = W[(2 * c2 + 1) * F_IN + k];
        }
        unsigned long long p;
        asm("mov.b64 %0, {%1, %2};" : "=l"(p) : "f"(lo), "f"(hi));
        Wp[i] = p;
    }

    int row = blockIdx.x * RPB + tid;
    unsigned long long acc[16];
    #pragma unroll
    for (int j = 0; j < 16; j++) acc[j] = 0ull;

    #pragma unroll 1
    for (int kt = 0; kt < 512; kt += KT) {
        __syncthreads();
        // stage x tile: 32 floats per row, shift/mask indexing
        {
            int r = tid >> 5;          // 8 rows per pass... (RPB/KT = 8 rows)
            int k = tid & 31;
            #pragma unroll
            for (int rr = 0; rr < KT; rr++) {      // 256 rows / 8 = 32 passes
                int lrow = r + (rr << 3);
                int gr = blockIdx.x * RPB + lrow;
                int gk = kt + k;
                float v = 0.f;
                if (gr < nN && gk < F_IN) v = x[(size_t)gr * F_IN + gk];
                xs[lrow * (KT + 1) + k] = v;
            }
        }
        __syncthreads();
        const float* xrow = &xs[tid * (KT + 1)];
        #pragma unroll
        for (int k = 0; k < KT; k++) {
            float xv = xrow[k];
            unsigned long long xx;
            asm("mov.b64 %0, {%1, %1};" : "=l"(xx) : "f"(xv));
            const ulonglong2* wr = (const ulonglong2*)&Wp[(kt + k) * 16];
            #pragma unroll
            for (int j = 0; j < 8; j++) {
                ulonglong2 wp = wr[j];
                asm("fma.rn.f32x2 %0, %1, %2, %0;" : "+l"(acc[2 * j])     : "l"(xx), "l"(wp.x));
                asm("fma.rn.f32x2 %0, %1, %2, %0;" : "+l"(acc[2 * j + 1]) : "l"(xx), "l"(wp.y));
            }
        }
    }

    if (row < nN) {
        float as = 0.f, ad = 0.f;
        unsigned long long* dst = (unsigned long long*)(g_xl + (size_t)row * CC);
        #pragma unroll
        for (int j = 0; j < 16; j++) {
            dst[j] = acc[j];
            float lo, hi;
            asm("mov.b64 {%0, %1}, %2;" : "=f"(lo), "=f"(hi) : "l"(acc[j]));
            as += lo * att_src[2 * j] + hi * att_src[2 * j + 1];
            ad += lo * att_dst[2 * j] + hi * att_dst[2 * j + 1];
        }
        g_asrc[row] = as;
        g_adst[row] = ad;
    }
}

// ---------------- scan (exclusive prefix of deg -> rowptr) ------------------
__global__ void k_scan1(int nN) {
    __shared__ int sh[1024];
    int tid = threadIdx.x;
    int i = blockIdx.x * 1024 + tid;
    int v = (i < nN) ? g_deg[i] : 0;
    sh[tid] = v;
    __syncthreads();
    for (int off = 1; off < 1024; off <<= 1) {
        int t = (tid >= off) ? sh[tid - off] : 0;
        __syncthreads();
        sh[tid] += t;
        __syncthreads();
    }
    if (i < nN) g_scan[i] = sh[tid];
    if (tid == 1023) g_bsum[blockIdx.x] = sh[1023];
}

__global__ void k_scan2(int nb, int nE) {
    int run = 0;
    for (int b = 0; b < nb; b++) {
        int t = g_bsum[b];
        g_boff[b] = run;
        run += t;
    }
    g_scalars[2] = g_scalars[0] / (float)nE;   // mean edge weight
}

// rowptr[i] = edge_scan[i] + i (self-loop slot per node). Self-loop entry is
// written here; cursor starts after it.
__global__ void k_scan3(int nN, int nE) {
    int i = blockIdx.x * blockDim.x + threadIdx.x;
    if (i < nN) {
        int ex = g_scan[i] - g_deg[i] + g_boff[i >> 10] + i;
        g_rowptr[i] = ex;
        g_cursor[i] = ex + 1;
        unsigned long long e = (unsigned long long)(unsigned)i |
            ((unsigned long long)__float_as_uint(g_scalars[2]) << 32);
        g_csr[ex] = e;
    }
    if (i == 0) g_rowptr[nN] = nN + nE;
}

// ---------------- fill CSR with packed (src, edge_weight) -------------------
// Branch-free: real edges only (self loops pre-placed by k_scan3).
__global__ void k_fill(const int* __restrict__ ei, const float* __restrict__ ew,
                       int nE) {
    int i = blockIdx.x * blockDim.x + threadIdx.x;
    if (i >= nE) return;
    int s = ei[i];
    int d = ei[nE + i];
    float w = ew[i];
    int pos = atomicAdd(&g_cursor[d], 1);
    unsigned long long e = (unsigned long long)(unsigned)s |
                           ((unsigned long long)__float_as_uint(w) << 32);
    g_csr[pos] = e;
}

// ---------------- gather: softmax-aggregate + fused heads -------------------
__global__ void __launch_bounds__(256)
k_gather(const float* __restrict__ bias_conv,
         const float* __restrict__ Wb, const float* __restrict__ bb,
         const float* __restrict__ Ww, const float* __restrict__ mask,
         float* __restrict__ out, int nN, int nE) {
    int warp = (blockIdx.x * blockDim.x + threadIdx.x) >> 5;
    int lane = threadIdx.x & 31;
    if (warp >= nN) return;
    int beg = g_rowptr[warp];
    int end = g_rowptr[warp + 1];
    float ad = g_adst[warp];
    float ke = g_scalars[1];
    float acc = 0.f, den = 0.f;

    int i = beg;
    for (; i + 4 <= end; i += 4) {
        unsigned long long e0 = g_csr[i];
        unsigned long long e1 = g_csr[i + 1];
        unsigned long long e2 = g_csr[i + 2];
        unsigned long long e3 = g_csr[i + 3];
        int s0 = (int)(unsigned)e0, s1 = (int)(unsigned)e1;
        int s2 = (int)(unsigned)e2, s3 = (int)(unsigned)e3;
        float v0 = g_xl[(size_t)s0 * CC + lane];
        float v1 = g_xl[(size_t)s1 * CC + lane];
        float v2 = g_xl[(size_t)s2 * CC + lane];
        float v3 = g_xl[(size_t)s3 * CC + lane];
        float as0 = g_asrc[s0], as1 = g_asrc[s1];
        float as2 = g_asrc[s2], as3 = g_asrc[s3];
        float a0 = fmaf(ke, __uint_as_float((unsigned)(e0 >> 32)), as0 + ad);
        float a1 = fmaf(ke, __uint_as_float((unsigned)(e1 >> 32)), as1 + ad);
        float a2 = fmaf(ke, __uint_as_float((unsigned)(e2 >> 32)), as2 + ad);
        float a3 = fmaf(ke, __uint_as_float((unsigned)(e3 >> 32)), as3 + ad);
        a0 = (a0 > 0.f) ? a0 : NEG * a0;
        a1 = (a1 > 0.f) ? a1 : NEG * a1;
        a2 = (a2 > 0.f) ? a2 : NEG * a2;
        a3 = (a3 > 0.f) ? a3 : NEG * a3;
        float x0 = __expf(a0), x1 = __expf(a1);
        float x2 = __expf(a2), x3 = __expf(a3);
        den += x0 + x1 + x2 + x3;
        acc = fmaf(x0, v0, acc);
        acc = fmaf(x1, v1, acc);
        acc = fmaf(x2, v2, acc);
        acc = fmaf(x3, v3, acc);
    }
    for (; i < end; i++) {
        unsigned long long e = g_csr[i];
        int s = (int)(unsigned)e;
        float v = g_xl[(size_t)s * CC + lane];
        float a = fmaf(ke, __uint_as_float((unsigned)(e >> 32)), g_asrc[s] + ad);
        a = (a > 0.f) ? a : NEG * a;
        float ex = __expf(a);
        den += ex;
        acc = fmaf(ex, v, acc);
    }

    float h = acc / den + bias_conv[lane];
    h = fmaxf(h, 0.f);
    float bsum = h * Wb[lane];
    float wsum = h * Ww[lane];
    #pragma unroll
    for (int o = 16; o > 0; o >>= 1) {
        bsum += __shfl_xor_sync(0xFFFFFFFFu, bsum, o);
        wsum += __shfl_xor_sync(0xFFFFFFFFu, wsum, o);
    }
    if (lane == 0) {
        g_hw[warp] = wsum;
        out[nE + warp] = (bsum + bb[0]) * mask[warp];
    }
}

// ---------------- edge output: 0.5*(hw[s]+hw[d]) + bw (vectorized) ---------
__global__ void k_edge(const int* __restrict__ ei, const float* __restrict__ bw,
                       float* __restrict__ out, int nE) {
    int q = blockIdx.x * blockDim.x + threadIdx.x;
    int nq = nE >> 2;
    float b = bw[0];
    if (q < nq) {
        int4 s4 = ((const int4*)ei)[q];
        int4 d4 = ((const int4*)(ei + nE))[q];
        float4 o;
        o.x = 0.5f * (g_hw[s4.x] + g_hw[d4.x]) + b;
        o.y = 0.5f * (g_hw[s4.y] + g_hw[d4.y]) + b;
        o.z = 0.5f * (g_hw[s4.z] + g_hw[d4.z]) + b;
        o.w = 0.5f * (g_hw[s4.w] + g_hw[d4.w]) + b;
        ((float4*)out)[q] = o;
    }
    // tail
    int i = (nq << 2) + q;
    if (q < (nE & 3)) {
        int idx = (nq << 2) + q;
        out[idx] = 0.5f * (g_hw[ei[idx]] + g_hw[ei[nE + idx]]) + b;
    }
    (void)i;
}

// ---------------- launch ----------------------------------------------------
extern "C" void kernel_launch(void* const* d_in, const int* in_sizes, int n_in,
                              void* d_out, int out_size) {
    const float* x         = (const float*)d_in[0];
    const int*   ei        = (const int*)d_in[1];
    const float* ew        = (const float*)d_in[2];
    const float* mask      = (const float*)d_in[3];
    const float* W_src     = (const float*)d_in[4];
    const float* att_src   = (const float*)d_in[5];
    const float* att_dst   = (const float*)d_in[6];
    const float* att_edge  = (const float*)d_in[7];
    const float* W_edge    = (const float*)d_in[8];
    const float* bias_conv = (const float*)d_in[9];
    const float* Wb        = (const float*)d_in[10];
    const float* bb        = (const float*)d_in[11];
    const float* Ww        = (const float*)d_in[12];
    const float* bw        = (const float*)d_in[13];
    float* out = (float*)d_out;

    int nN = in_sizes[3];            // input_mask: [N,1]
    int nE = in_sizes[2];            // edge_weight: [E,1]

    const int smem = 512 * 16 * 8 + RPB * (KT + 1) * 4;   // 99328 B
    cudaFuncSetAttribute((const void*)k_gemm,
                         cudaFuncAttributeMaxDynamicSharedMemorySize, smem);

    int nb = (nN + 1023) / 1024;
    // Order chosen so k_gemm is my 4th launch -> ncu's profiled slot.
    k_init<<<(nN + 255) / 256, 256>>>(W_edge, att_edge, nN);
    k_deg_mean<<<2048, 256>>>(ei, ew, nE);
    k_scan1<<<nb, 1024>>>(nN);
    k_gemm<<<(nN + RPB - 1) / RPB, RPB, smem>>>(x, W_src, att_src, att_dst, nN);
    k_scan2<<<1, 1>>>(nb, nE);
    k_scan3<<<(nN + 255) / 256, 256>>>(nN, nE);
    k_fill<<<(nE + 255) / 256, 256>>>(ei, ew, nE);
    k_gather<<<(nN + 7) / 8, 256>>>(bias_conv, Wb, bb, Ww, mask, out, nN, nE);
    k_edge<<<((nE >> 2) + 255) / 256, 256>>>(ei, bw, out, nE);
}